// round 3
// baseline (speedup 1.0000x reference)
#include <cuda_runtime.h>

#define BATCH 8
#define C 256
#define OC2 512
#define H 96
#define W 96
#define HW 9216          // 96*96
#define HP 98
#define PP 9604          // 98*98
#define POUT 256
#define EPS 1e-5f

// ---------------- scratch (static device globals; no allocation) -------------
__device__ float g_wr[9 * C * OC2];          // weights reordered [tap][ic][oc]   (4.7 MB)
__device__ float g_wpt[C * POUT];            // pointwise weights [c][o]          (256 KB)
__device__ float g_off[BATCH * OC2 * PP];    // offset conv output                (157 MB)
__device__ float g_xd[BATCH * C * HW];       // deform-sampled feature map        (75.5 MB)
__device__ float g_sums[2 * C];              // per-channel [sum, sumsq]
__device__ float g_scale[C];
__device__ float g_shift[C];

// ---------------- kernel 0: weight pre-transpose + stats re-zero -------------
__global__ void k_prep(const float* __restrict__ w, const float* __restrict__ wpw) {
    int i = blockIdx.x * 256 + threadIdx.x;
    if (i < 2 * C) g_sums[i] = 0.f;          // MUST re-zero every call (graph replay)
    if (i < OC2 * C * 9) {
        int oc  = i / (C * 9);
        int r   = i - oc * (C * 9);
        int ic  = r / 9;
        int tap = r - ic * 9;
        g_wr[(tap * C + ic) * OC2 + oc] = w[i];
    }
    if (i < POUT * C) {
        int o = i >> 8;      // POUT == 256
        int c = i & 255;     // C == 256
        g_wpt[c * POUT + o] = wpw[i];
    }
}

// ---------------- kernel 1: offset conv as 9 shifted GEMMs -------------------
// C[oc][p] += sum_ic W[tap][ic][oc] * X[ic][shifted p], accumulated over taps.
// Block tile: 128 oc x 64 p, BK=16. Thread tile 8x4. 256 threads.
__global__ __launch_bounds__(256) void k_offconv(const float* __restrict__ x) {
    __shared__ float As[16][128];
    __shared__ float Bs[16][64];

    const int t   = threadIdx.x;
    const int b   = blockIdx.z;
    const int oc0 = blockIdx.y * 128;
    const int p0  = blockIdx.x * 64;

    const int tp  = t & 15;     // p-frag group   -> cols tp*4 .. tp*4+3
    const int to  = t >> 4;     // oc-frag group  -> rows to*8 .. to*8+7

    const int ppl = t & 63;     // B-tile load column
    const int kk0 = t >> 6;     // B-tile load row base (0..3)
    const int P   = p0 + ppl;
    const bool pv = (P < PP);
    const int yy  = P / HP;
    const int xx  = P - yy * HP;

    const float* xb = x + (size_t)b * C * HW;

    float acc[8][4];
#pragma unroll
    for (int i = 0; i < 8; i++)
#pragma unroll
        for (int j = 0; j < 4; j++) acc[i][j] = 0.f;

#pragma unroll 1
    for (int tap = 0; tap < 9; ++tap) {
        const int ky = tap / 3;
        const int kx = tap - ky * 3;
        const int Y  = yy + ky - 2;           // source row in original 96x96 map
        const int X  = xx + kx - 2;
        const bool inb = pv && ((unsigned)Y < (unsigned)H) && ((unsigned)X < (unsigned)W);
        const int sp = Y * W + X;
        const float* wt = g_wr + (size_t)tap * C * OC2;

#pragma unroll 1
        for (int ic0 = 0; ic0 < C; ic0 += 16) {
            __syncthreads();
#pragma unroll
            for (int j = 0; j < 8; ++j) {     // A tile: 16x128, coalesced over oc
                int idx = t + j * 256;
                int kk  = idx >> 7;
                int oc  = idx & 127;
                As[kk][oc] = wt[(ic0 + kk) * OC2 + oc0 + oc];
            }
#pragma unroll
            for (int j = 0; j < 4; ++j) {     // B tile: 16x64, coalesced over p
                int kk = kk0 + j * 4;
                Bs[kk][ppl] = inb ? __ldg(xb + (size_t)(ic0 + kk) * HW + sp) : 0.f;
            }
            __syncthreads();
#pragma unroll
            for (int kk = 0; kk < 16; ++kk) {
                float4 a0 = *(const float4*)&As[kk][to * 8];
                float4 a1 = *(const float4*)&As[kk][to * 8 + 4];
                float4 bb = *(const float4*)&Bs[kk][tp * 4];
                float av[8] = {a0.x, a0.y, a0.z, a0.w, a1.x, a1.y, a1.z, a1.w};
                float bv[4] = {bb.x, bb.y, bb.z, bb.w};
#pragma unroll
                for (int i = 0; i < 8; i++)
#pragma unroll
                    for (int j = 0; j < 4; j++)
                        acc[i][j] = fmaf(av[i], bv[j], acc[i][j]);
            }
        }
    }

    const int pw = p0 + tp * 4;
    const bool full = (pw + 3 < PP);
#pragma unroll
    for (int i = 0; i < 8; i++) {
        int oc = oc0 + to * 8 + i;
        float* dst = g_off + ((size_t)b * OC2 + oc) * PP + pw;
        if (full) {
            *(float4*)dst = make_float4(acc[i][0], acc[i][1], acc[i][2], acc[i][3]);
        } else {
#pragma unroll
            for (int j = 0; j < 4; j++)
                if (pw + j < PP) dst[j] = acc[i][j];
        }
    }
}

// ---------------- kernel 2: bilinear deform sampling + BN partial sums -------
__global__ __launch_bounds__(256) void k_sample(const float* __restrict__ x) {
    const int bc = blockIdx.x;           // b*C + c
    const int b  = bc >> 8;
    const int c  = bc & 255;
    const float* xc = x + (size_t)bc * HW;
    // channel pair (2c, 2c+1) is contiguous: flat element 2p indexes directly.
    const float* offb = g_off + ((size_t)b * OC2 + 2 * c) * PP;

    float s1 = 0.f, s2 = 0.f;
    for (int i = threadIdx.x; i < HW; i += 256) {
        int iy = i / W;
        int ix = i - iy * W;
        int yy = iy + 1, xx = ix + 1;            // padded-grid coords (interior)
        int p2 = 2 * (yy * HP + xx);
        float oy = __ldg(offb + p2);
        float ox = __ldg(offb + p2 + 1);
        float cy = fminf(fmaxf((float)yy + oy, 0.f), 97.f);
        float cx = fminf(fmaxf((float)xx + ox, 0.f), 97.f);
        float fy = floorf(cy), fx = floorf(cx);
        int y0 = (int)fy, x0 = (int)fx;
        int y1 = min(y0 + 1, 97), x1 = min(x0 + 1, 97);
        float dy = cy - fy, dx = cx - fx;
        // padded map: border (index 0 or 97) is zero
        float v00 = (y0 >= 1 && y0 <= 96 && x0 >= 1 && x0 <= 96) ? __ldg(xc + (y0 - 1) * W + (x0 - 1)) : 0.f;
        float v01 = (y0 >= 1 && y0 <= 96 && x1 >= 1 && x1 <= 96) ? __ldg(xc + (y0 - 1) * W + (x1 - 1)) : 0.f;
        float v10 = (y1 >= 1 && y1 <= 96 && x0 >= 1 && x0 <= 96) ? __ldg(xc + (y1 - 1) * W + (x0 - 1)) : 0.f;
        float v11 = (y1 >= 1 && y1 <= 96 && x1 >= 1 && x1 <= 96) ? __ldg(xc + (y1 - 1) * W + (x1 - 1)) : 0.f;
        float top = v00 + (v01 - v00) * dx;
        float bot = v10 + (v11 - v10) * dx;
        float v   = top + (bot - top) * dy;
        g_xd[(size_t)bc * HW + i] = v;
        s1 += v;
        s2 += v * v;
    }
#pragma unroll
    for (int off = 16; off > 0; off >>= 1) {
        s1 += __shfl_down_sync(0xffffffffu, s1, off);
        s2 += __shfl_down_sync(0xffffffffu, s2, off);
    }
    __shared__ float r1[8], r2[8];
    int lane = threadIdx.x & 31, wid = threadIdx.x >> 5;
    if (lane == 0) { r1[wid] = s1; r2[wid] = s2; }
    __syncthreads();
    if (threadIdx.x == 0) {
        float a = 0.f, q = 0.f;
#pragma unroll
        for (int i = 0; i < 8; i++) { a += r1[i]; q += r2[i]; }
        atomicAdd(&g_sums[2 * c], a);
        atomicAdd(&g_sums[2 * c + 1], q);
    }
}

// ---------------- kernel 3: BN scale/shift from batch stats ------------------
__global__ void k_bn(const float* __restrict__ gamma, const float* __restrict__ beta) {
    int c = threadIdx.x;
    const float invn = 1.f / (float)(BATCH * HW);
    float mean = g_sums[2 * c] * invn;
    float var  = g_sums[2 * c + 1] * invn - mean * mean;
    float inv  = rsqrtf(var + EPS);
    float sc   = gamma[c] * inv;
    g_scale[c] = sc;
    g_shift[c] = fmaf(-mean, sc, beta[c]);
}

// ---------------- kernel 4: pointwise 1x1 GEMM, fused BN + ReLU --------------
// Block tile 128 (out ch) x 64 p, BK=16, thread tile 8x4, 256 threads.
__global__ __launch_bounds__(256) void k_pw(float* __restrict__ out) {
    __shared__ float As[16][128];
    __shared__ float Bs[16][64];

    const int t   = threadIdx.x;
    const int b   = blockIdx.z;
    const int o0  = blockIdx.y * 128;
    const int p0  = blockIdx.x * 64;
    const int tp  = t & 15;
    const int to  = t >> 4;
    const int ppl = t & 63;
    const int kk0 = t >> 6;

    const float* xb = g_xd + (size_t)b * C * HW;

    float acc[8][4];
#pragma unroll
    for (int i = 0; i < 8; i++)
#pragma unroll
        for (int j = 0; j < 4; j++) acc[i][j] = 0.f;

#pragma unroll 1
    for (int ic0 = 0; ic0 < C; ic0 += 16) {
        __syncthreads();
#pragma unroll
        for (int j = 0; j < 8; ++j) {
            int idx = t + j * 256;
            int kk  = idx >> 7;
            int oc  = idx & 127;
            As[kk][oc] = g_wpt[(ic0 + kk) * POUT + o0 + oc];
        }
#pragma unroll
        for (int j = 0; j < 4; ++j) {
            int kk = kk0 + j * 4;
            int ic = ic0 + kk;
            float v = __ldg(xb + (size_t)ic * HW + p0 + ppl);
            v = fmaxf(fmaf(v, __ldg(&g_scale[ic]), __ldg(&g_shift[ic])), 0.f);
            Bs[kk][ppl] = v;
        }
        __syncthreads();
#pragma unroll
        for (int kk = 0; kk < 16; ++kk) {
            float4 a0 = *(const float4*)&As[kk][to * 8];
            float4 a1 = *(const float4*)&As[kk][to * 8 + 4];
            float4 bb = *(const float4*)&Bs[kk][tp * 4];
            float av[8] = {a0.x, a0.y, a0.z, a0.w, a1.x, a1.y, a1.z, a1.w};
            float bv[4] = {bb.x, bb.y, bb.z, bb.w};
#pragma unroll
            for (int i = 0; i < 8; i++)
#pragma unroll
                for (int j = 0; j < 4; j++)
                    acc[i][j] = fmaf(av[i], bv[j], acc[i][j]);
        }
    }

    const int pw = p0 + tp * 4;
#pragma unroll
    for (int i = 0; i < 8; i++) {
        float* dst = out + ((size_t)b * POUT + o0 + to * 8 + i) * HW + pw;
        *(float4*)dst = make_float4(acc[i][0], acc[i][1], acc[i][2], acc[i][3]);
    }
}

// ---------------- launch -----------------------------------------------------
extern "C" void kernel_launch(void* const* d_in, const int* in_sizes, int n_in,
                              void* d_out, int out_size) {
    const float* x     = (const float*)d_in[0];
    const float* w_off = (const float*)d_in[1];
    const float* gamma = (const float*)d_in[2];
    const float* beta  = (const float*)d_in[3];
    const float* w_pw  = (const float*)d_in[4];
    float* out = (float*)d_out;

    k_prep<<<(OC2 * C * 9 + 255) / 256, 256>>>(w_off, w_pw);
    k_offconv<<<dim3((PP + 63) / 64, OC2 / 128, BATCH), 256>>>(x);
    k_sample<<<BATCH * C, 256>>>(x);
    k_bn<<<1, C>>>(gamma, beta);
    k_pw<<<dim3(HW / 64, POUT / 128, BATCH), 256>>>(out);
}

// round 4
// speedup vs baseline: 1.9607x; 1.9607x over previous
#include <cuda_runtime.h>

#define BATCH 8
#define C 256
#define OC2 512
#define H 96
#define W 96
#define HW 9216          // 96*96
#define HP 98
#define PP 9604          // 98*98
#define POUT 256
#define EPS 1e-5f

// ---------------- scratch (static device globals; no allocation) -------------
__device__ float g_wr[9 * C * OC2];          // weights reordered [tap][ic][oc]
__device__ float g_wpt[C * POUT];            // pointwise weights [c][o]
__device__ float g_off[BATCH * OC2 * PP];    // offset conv output
__device__ float g_xd[BATCH * C * HW];       // deform-sampled feature map
__device__ float g_sums[2 * C];              // per-channel [sum, sumsq]
__device__ float g_scale[C];
__device__ float g_shift[C];

__device__ __forceinline__ unsigned f2tf32(float f) {
    unsigned u;
    asm("cvt.rna.tf32.f32 %0, %1;" : "=r"(u) : "f"(f));
    return u;
}

// ---------------- kernel 0: weight pre-transpose + stats re-zero -------------
__global__ void k_prep(const float* __restrict__ w, const float* __restrict__ wpw) {
    int i = blockIdx.x * 256 + threadIdx.x;
    if (i < 2 * C) g_sums[i] = 0.f;          // MUST re-zero every call (graph replay)
    if (i < OC2 * C * 9) {
        int oc  = i / (C * 9);
        int r   = i - oc * (C * 9);
        int ic  = r / 9;
        int tap = r - ic * 9;
        g_wr[(tap * C + ic) * OC2 + oc] = w[i];
    }
    if (i < POUT * C) {
        int o = i >> 8;      // POUT == 256
        int c = i & 255;     // C == 256
        g_wpt[c * POUT + o] = wpw[i];
    }
}

// ---------------- kernel 1: offset conv, TF32 mma.sync -----------------------
// 9 shifted GEMMs: off[oc][p] += sum_ic W[tap][ic][oc] * X[ic][shift_tap(p)]
// Block tile 256(oc) x 128(p), BK=16. 512 threads = 16 warps (4 oc x 4 p),
// warp tile 64x32 -> 4 m-tiles x 4 n-tiles of m16n8k8.
#define ASTR 260   // 256 pad->  bank shift 4 per k-row: conflict-free A frags
#define BSTR 136   // 128 pad->  bank shift 8 per k-row: conflict-free B frags
__global__ __launch_bounds__(512, 1) void k_offconv(const float* __restrict__ x) {
    __shared__ unsigned As[16 * ASTR];   // [k][oc]
    __shared__ unsigned Bs[16 * BSTR];   // [k][p]

    const int t    = threadIdx.x;
    const int warp = t >> 5;
    const int lane = t & 31;
    const int gr   = lane >> 2;          // 0..7
    const int gc   = lane & 3;           // 0..3
    const int w_oc = (warp >> 2) * 64;   // 0,64,128,192
    const int w_p  = (warp & 3) * 32;    // 0,32,64,96

    const int b    = blockIdx.z;
    const int oc0  = blockIdx.y * 256;
    const int p0   = blockIdx.x * 128;

    // B loader: col = t&127, rows kb + 4j
    const int ppl = t & 127;
    const int kb  = t >> 7;              // 0..3
    const int P   = p0 + ppl;
    const bool pv = (P < PP);
    const int yy  = P / HP;
    const int xx  = P - yy * HP;
    // A loader: col = t&255, rows ka + 2j
    const int ocl = t & 255;
    const int ka  = t >> 8;              // 0..1

    const float* xb = x + (size_t)b * C * HW;

    float acc[4][4][4];
#pragma unroll
    for (int i = 0; i < 4; i++)
#pragma unroll
        for (int j = 0; j < 4; j++)
#pragma unroll
            for (int r = 0; r < 4; r++) acc[i][j][r] = 0.f;

#pragma unroll 1
    for (int tap = 0; tap < 9; ++tap) {
        const int ky = tap / 3;
        const int kx = tap - ky * 3;
        const int Y  = yy + ky - 2;
        const int X  = xx + kx - 2;
        const bool inb = pv && ((unsigned)Y < (unsigned)H) && ((unsigned)X < (unsigned)W);
        const int sp = Y * W + X;
        const float* wt = g_wr + (size_t)tap * C * OC2;

#pragma unroll 1
        for (int ic0 = 0; ic0 < C; ic0 += 16) {
            __syncthreads();
#pragma unroll
            for (int j = 0; j < 8; ++j) {      // A: 16x256, coalesced over oc
                int kk = ka + j * 2;
                As[kk * ASTR + ocl] = f2tf32(wt[(size_t)(ic0 + kk) * OC2 + oc0 + ocl]);
            }
#pragma unroll
            for (int j = 0; j < 4; ++j) {      // B: 16x128, coalesced over p
                int kk = kb + j * 4;
                Bs[kk * BSTR + ppl] = f2tf32(inb ? __ldg(xb + (size_t)(ic0 + kk) * HW + sp) : 0.f);
            }
            __syncthreads();

#pragma unroll
            for (int ks = 0; ks < 16; ks += 8) {
                unsigned af[4][4], bf[4][2];
#pragma unroll
                for (int mi = 0; mi < 4; ++mi) {
                    int oc = w_oc + mi * 16 + gr;
                    af[mi][0] = As[(ks + gc)     * ASTR + oc];
                    af[mi][1] = As[(ks + gc)     * ASTR + oc + 8];
                    af[mi][2] = As[(ks + gc + 4) * ASTR + oc];
                    af[mi][3] = As[(ks + gc + 4) * ASTR + oc + 8];
                }
#pragma unroll
                for (int nj = 0; nj < 4; ++nj) {
                    int pc = w_p + nj * 8 + gr;
                    bf[nj][0] = Bs[(ks + gc)     * BSTR + pc];
                    bf[nj][1] = Bs[(ks + gc + 4) * BSTR + pc];
                }
#pragma unroll
                for (int mi = 0; mi < 4; ++mi)
#pragma unroll
                    for (int nj = 0; nj < 4; ++nj)
                        asm volatile(
                            "mma.sync.aligned.m16n8k8.row.col.f32.tf32.tf32.f32 "
                            "{%0,%1,%2,%3}, {%4,%5,%6,%7}, {%8,%9}, {%0,%1,%2,%3};"
                            : "+f"(acc[mi][nj][0]), "+f"(acc[mi][nj][1]),
                              "+f"(acc[mi][nj][2]), "+f"(acc[mi][nj][3])
                            : "r"(af[mi][0]), "r"(af[mi][1]), "r"(af[mi][2]), "r"(af[mi][3]),
                              "r"(bf[nj][0]), "r"(bf[nj][1]));
            }
        }
    }

    // store: c0,c1 -> (gr, 2gc..2gc+1); c2,c3 -> (gr+8, ...)
#pragma unroll
    for (int mi = 0; mi < 4; ++mi) {
#pragma unroll
        for (int nj = 0; nj < 4; ++nj) {
            int row0 = oc0 + w_oc + mi * 16 + gr;
            int col  = p0 + w_p + nj * 8 + 2 * gc;
            float* d0 = g_off + ((size_t)b * OC2 + row0) * PP + col;
            float* d1 = d0 + 8 * PP;
            if (col + 1 < PP) {
                *(float2*)d0 = make_float2(acc[mi][nj][0], acc[mi][nj][1]);
                *(float2*)d1 = make_float2(acc[mi][nj][2], acc[mi][nj][3]);
            } else if (col < PP) {
                d0[0] = acc[mi][nj][0];
                d1[0] = acc[mi][nj][2];
            }
        }
    }
}

// ---------------- kernel 2: bilinear deform sampling + BN partial sums -------
__global__ __launch_bounds__(256) void k_sample(const float* __restrict__ x) {
    const int bc = blockIdx.x;           // b*C + c
    const int b  = bc >> 8;
    const int c  = bc & 255;
    const float* xc = x + (size_t)bc * HW;
    const float* offb = g_off + ((size_t)b * OC2 + 2 * c) * PP;

    float s1 = 0.f, s2 = 0.f;
    for (int i = threadIdx.x; i < HW; i += 256) {
        int iy = i / W;
        int ix = i - iy * W;
        int yy = iy + 1, xx = ix + 1;
        int p2 = 2 * (yy * HP + xx);
        float oy = __ldg(offb + p2);
        float ox = __ldg(offb + p2 + 1);
        float cy = fminf(fmaxf((float)yy + oy, 0.f), 97.f);
        float cx = fminf(fmaxf((float)xx + ox, 0.f), 97.f);
        float fy = floorf(cy), fx = floorf(cx);
        int y0 = (int)fy, x0 = (int)fx;
        int y1 = min(y0 + 1, 97), x1 = min(x0 + 1, 97);
        float dy = cy - fy, dx = cx - fx;
        float v00 = (y0 >= 1 && y0 <= 96 && x0 >= 1 && x0 <= 96) ? __ldg(xc + (y0 - 1) * W + (x0 - 1)) : 0.f;
        float v01 = (y0 >= 1 && y0 <= 96 && x1 >= 1 && x1 <= 96) ? __ldg(xc + (y0 - 1) * W + (x1 - 1)) : 0.f;
        float v10 = (y1 >= 1 && y1 <= 96 && x0 >= 1 && x0 <= 96) ? __ldg(xc + (y1 - 1) * W + (x0 - 1)) : 0.f;
        float v11 = (y1 >= 1 && y1 <= 96 && x1 >= 1 && x1 <= 96) ? __ldg(xc + (y1 - 1) * W + (x1 - 1)) : 0.f;
        float top = v00 + (v01 - v00) * dx;
        float bot = v10 + (v11 - v10) * dx;
        float v   = top + (bot - top) * dy;
        g_xd[(size_t)bc * HW + i] = v;
        s1 += v;
        s2 += v * v;
    }
#pragma unroll
    for (int off = 16; off > 0; off >>= 1) {
        s1 += __shfl_down_sync(0xffffffffu, s1, off);
        s2 += __shfl_down_sync(0xffffffffu, s2, off);
    }
    __shared__ float r1[8], r2[8];
    int lane = threadIdx.x & 31, wid = threadIdx.x >> 5;
    if (lane == 0) { r1[wid] = s1; r2[wid] = s2; }
    __syncthreads();
    if (threadIdx.x == 0) {
        float a = 0.f, q = 0.f;
#pragma unroll
        for (int i = 0; i < 8; i++) { a += r1[i]; q += r2[i]; }
        atomicAdd(&g_sums[2 * c], a);
        atomicAdd(&g_sums[2 * c + 1], q);
    }
}

// ---------------- kernel 3: BN scale/shift from batch stats ------------------
__global__ void k_bn(const float* __restrict__ gamma, const float* __restrict__ beta) {
    int c = threadIdx.x;
    const float invn = 1.f / (float)(BATCH * HW);
    float mean = g_sums[2 * c] * invn;
    float var  = g_sums[2 * c + 1] * invn - mean * mean;
    float inv  = rsqrtf(var + EPS);
    float sc   = gamma[c] * inv;
    g_scale[c] = sc;
    g_shift[c] = fmaf(-mean, sc, beta[c]);
}

// ---------------- kernel 4: pointwise 1x1 GEMM, fused BN + ReLU --------------
__global__ __launch_bounds__(256) void k_pw(float* __restrict__ out) {
    __shared__ float As[16][128];
    __shared__ float Bs[16][64];

    const int t   = threadIdx.x;
    const int b   = blockIdx.z;
    const int o0  = blockIdx.y * 128;
    const int p0  = blockIdx.x * 64;
    const int tp  = t & 15;
    const int to  = t >> 4;
    const int ppl = t & 63;
    const int kk0 = t >> 6;

    const float* xb = g_xd + (size_t)b * C * HW;

    float acc[8][4];
#pragma unroll
    for (int i = 0; i < 8; i++)
#pragma unroll
        for (int j = 0; j < 4; j++) acc[i][j] = 0.f;

#pragma unroll 1
    for (int ic0 = 0; ic0 < C; ic0 += 16) {
        __syncthreads();
#pragma unroll
        for (int j = 0; j < 8; ++j) {
            int idx = t + j * 256;
            int kk  = idx >> 7;
            int oc  = idx & 127;
            As[kk][oc] = g_wpt[(ic0 + kk) * POUT + o0 + oc];
        }
#pragma unroll
        for (int j = 0; j < 4; ++j) {
            int kk = kk0 + j * 4;
            int ic = ic0 + kk;
            float v = __ldg(xb + (size_t)ic * HW + p0 + ppl);
            v = fmaxf(fmaf(v, __ldg(&g_scale[ic]), __ldg(&g_shift[ic])), 0.f);
            Bs[kk][ppl] = v;
        }
        __syncthreads();
#pragma unroll
        for (int kk = 0; kk < 16; ++kk) {
            float4 a0 = *(const float4*)&As[kk][to * 8];
            float4 a1 = *(const float4*)&As[kk][to * 8 + 4];
            float4 bb = *(const float4*)&Bs[kk][tp * 4];
            float av[8] = {a0.x, a0.y, a0.z, a0.w, a1.x, a1.y, a1.z, a1.w};
            float bv[4] = {bb.x, bb.y, bb.z, bb.w};
#pragma unroll
            for (int i = 0; i < 8; i++)
#pragma unroll
                for (int j = 0; j < 4; j++)
                    acc[i][j] = fmaf(av[i], bv[j], acc[i][j]);
        }
    }

    const int pw = p0 + tp * 4;
#pragma unroll
    for (int i = 0; i < 8; i++) {
        float* dst = out + ((size_t)b * POUT + o0 + to * 8 + i) * HW + pw;
        *(float4*)dst = make_float4(acc[i][0], acc[i][1], acc[i][2], acc[i][3]);
    }
}

// ---------------- launch -----------------------------------------------------
extern "C" void kernel_launch(void* const* d_in, const int* in_sizes, int n_in,
                              void* d_out, int out_size) {
    const float* x     = (const float*)d_in[0];
    const float* w_off = (const float*)d_in[1];
    const float* gamma = (const float*)d_in[2];
    const float* beta  = (const float*)d_in[3];
    const float* w_pw  = (const float*)d_in[4];
    float* out = (float*)d_out;

    k_prep<<<(OC2 * C * 9 + 255) / 256, 256>>>(w_off, w_pw);
    k_offconv<<<dim3((PP + 127) / 128, OC2 / 256, BATCH), 512>>>(x);
    k_sample<<<BATCH * C, 256>>>(x);
    k_bn<<<1, C>>>(gamma, beta);
    k_pw<<<dim3(HW / 64, POUT / 128, BATCH), 256>>>(out);
}